// round 11
// baseline (speedup 1.0000x reference)
#include <cuda_runtime.h>

#define N_BINS 10
#define GRID_BLOCKS 888        // 148 SMs * 6 blocks
#define BLOCK_THREADS 128
#define TILE_ROWS 32           // rows per block-tile (16KB)

// Global scratch (no allocations allowed). Zero-initialized at module load;
// the last finishing block resets them, so "zeroed at entry" holds across
// graph replays.
__device__ double g_cnt[N_BINS];
__device__ double g_conf[N_BINS];
__device__ double g_acc[N_BINS];
__device__ unsigned g_done;

// Raw ex2; used identically at both exp sites so recomputation is bit-exact.
__device__ __forceinline__ float expf_raw(float x) {
    float t = __fmul_rn(x, 1.4426950408889634f);
    float r;
    asm("ex2.approx.f32 %0, %1;" : "=f"(r) : "f"(t));
    return r;
}

__device__ __forceinline__ void cp_async16(void* smem, const void* gmem) {
    unsigned s = (unsigned)__cvta_generic_to_shared(smem);
    asm volatile("cp.async.cg.shared.global [%0], [%1], 16;"
                 :: "r"(s), "l"(gmem) : "memory");
}
__device__ __forceinline__ void cp_commit() {
    asm volatile("cp.async.commit_group;" ::: "memory");
}
__device__ __forceinline__ void cp_wait1() {
    asm volatile("cp.async.wait_group 1;" ::: "memory");
}

__global__ void __launch_bounds__(BLOCK_THREADS) ece_fused(
    const float* __restrict__ logits,
    const int* __restrict__ labels,
    int n_rows,
    float* __restrict__ out)
{
    // Double-buffered tile: [buf][row][chunk], chunk c of row r stored at
    // c ^ (r & 7) -> conflict-free LDS.128 for the quarter-row scan.
    __shared__ float4 buf[2][TILE_ROWS][32];     // 2 x 16KB
    __shared__ float pad_s[4][TILE_ROWS];        // quarter partial sums
    __shared__ float pad_m[4][TILE_ROWS];        // quarter partial maxes
    __shared__ float s_c[N_BINS], s_f[N_BINS], s_a[N_BINS];

    const int tid = threadIdx.x;
    if (tid < N_BINS) { s_c[tid] = 0.0f; s_f[tid] = 0.0f; s_a[tid] = 0.0f; }

    const int row = tid & 31;          // my row within the tile
    const int q   = tid >> 5;          // my quarter (chunks q*8 .. q*8+7)
    const int rx  = row & 7;
    const float4* __restrict__ lrows = (const float4*)logits;

    const int n_tiles = (n_rows + TILE_ROWS - 1) / TILE_ROWS;

    // ---- tile loader: 8 cp.asyncs per thread (1024 slots / 128 threads) ----
    auto load_tile = [&](int d, int t) {
        const int base = t * TILE_ROWS;
        const float4* g = lrows + (size_t)base * 32;
        #pragma unroll
        for (int k = 0; k < 8; k++) {
            int f = tid + k * 128;
            int r = f >> 5, c = f & 31;
            float4* dst = &buf[d][r][c ^ (r & 7)];
            if (base + r < n_rows) cp_async16(dst, g + (size_t)r * 32 + c);
            else *dst = make_float4(0.f, 0.f, 0.f, 0.f);
        }
        cp_commit();
    };

    int t = blockIdx.x;
    int d = 0;
    if (t < n_tiles) load_tile(0, t);
    else cp_commit();                  // keep group accounting uniform

    __syncthreads();                   // covers s_* init too

    for (; t < n_tiles; t += GRID_BLOCKS, d ^= 1) {
        // Prefetch next tile into the other buffer (freed last iteration).
        int tn = t + GRID_BLOCKS;
        if (tn < n_tiles) load_tile(d ^ 1, tn);
        else cp_commit();              // empty group so wait_group 1 is uniform

        cp_wait1();                    // tile t's group complete
        __syncthreads();               // visible block-wide

        // ---- compute: serial scan of my quarter-row, zero collectives ----
        const float4* R = buf[d][row];
        float s0 = 0.f, s1 = 0.f, m0 = 0.f, m1 = 0.f;   // exps > 0
        #pragma unroll
        for (int j = 0; j < 8; j++) {
            float4 v = R[q * 8 + (j ^ rx)];
            float e0 = expf_raw(v.x), e1 = expf_raw(v.y);
            float e2 = expf_raw(v.z), e3 = expf_raw(v.w);
            s0 += e0 + e1;  s1 += e2 + e3;
            m0 = fmaxf(m0, fmaxf(e0, e1));
            m1 = fmaxf(m1, fmaxf(e2, e3));
        }
        pad_s[q][row] = s0 + s1;
        pad_m[q][row] = fmaxf(m0, m1);
        __syncthreads();

        // ---- epilogue: one thread per row combines quarters + bins ----
        if (tid < TILE_ROWS) {
            int gr = t * TILE_ROWS + tid;
            if (gr < n_rows) {
                float s  = (pad_s[0][tid] + pad_s[1][tid])
                         + (pad_s[2][tid] + pad_s[3][tid]);
                float mx = fmaxf(fmaxf(pad_m[0][tid], pad_m[1][tid]),
                                 fmaxf(pad_m[2][tid], pad_m[3][tid]));
                int lab = labels[gr];
                // label element: scalar smem read + bit-exact exp recompute
                float lv = ((const float*)&buf[d][tid][(lab >> 2) ^ (tid & 7)])
                               [lab & 3];
                float le = expf_raw(lv);

                float conf = __fdividef(mx, s);
                int b = min((int)ceilf(conf * 10.0f), N_BINS) - 1;
                b = max(b, 0);
                atomicAdd(&s_c[b], 1.0f);
                atomicAdd(&s_f[b], conf);
                atomicAdd(&s_a[b], (le == mx) ? 1.0f : 0.0f);
            }
        }
        __syncthreads();   // epilogue's buf[d] read done before next prefetch
    }

    // ---- block -> global reduction ----
    __syncthreads();
    if (tid < N_BINS) {
        atomicAdd(&g_cnt[tid],  (double)s_c[tid]);
        atomicAdd(&g_conf[tid], (double)s_f[tid]);
        atomicAdd(&g_acc[tid],  (double)s_a[tid]);
        __threadfence();               // order bin atomics before done-ticket
    }
    __syncthreads();

    // Last block finalizes and resets scratch for the next graph replay.
    if (tid == 0) {
        unsigned ticket = atomicAdd(&g_done, 1u);
        if (ticket == GRID_BLOCKS - 1) {
            double ece = 0.0, oe = 0.0;
            #pragma unroll
            for (int i = 0; i < N_BINS; i++) {
                double cnt = atomicAdd(&g_cnt[i],  0.0);
                double cf  = atomicAdd(&g_conf[i], 0.0);
                double ac  = atomicAdd(&g_acc[i],  0.0);
                bool nonempty = cnt > 0.0;
                double prop  = cnt / (double)n_rows;
                double denom = nonempty ? cnt : 1.0;
                double accb  = nonempty ? ac / denom : 0.0;
                double cfb   = nonempty ? cf / denom : 0.0;
                double CE    = cfb - accb;
                double absCE = nonempty ? fabs(CE) : 0.0;
                ece += absCE * prop;
                oe  += (nonempty ? cfb * fmax(CE, 0.0) : 0.0) * prop;
                out[1 + i]  = (float)accb;
                out[12 + i] = (float)prop;
                out[22 + i] = (float)absCE;
                g_cnt[i] = 0.0; g_conf[i] = 0.0; g_acc[i] = 0.0;
            }
            out[0]  = (float)ece;
            out[11] = (float)oe;
            g_done = 0u;
            __threadfence();
        }
    }
}

extern "C" void kernel_launch(void* const* d_in, const int* in_sizes, int n_in,
                              void* d_out, int out_size) {
    const float* logits = (const float*)d_in[0];
    const int*   labels = (const int*)d_in[1];
    float*       out    = (float*)d_out;

    int n_rows = in_sizes[0] / 128;   // C = 128

    ece_fused<<<GRID_BLOCKS, BLOCK_THREADS>>>(logits, labels, n_rows, out);
}